// round 11
// baseline (speedup 1.0000x reference)
#include <cuda_runtime.h>
#include <cuda_bf16.h>
#include <math.h>

#define SEQ    2048
#define EMB    1024
#define STATE  1024
#define QIN    2048
#define QUERY  256
#define NKB    10000
#define NKBP   10240
#define VALUE  512
#define NTOK   32000
#define DECIN  2560
#define GATES  4096
#define LIN    1536

#define NBLK   148
#define NTHR   512
#define NWTOT  (NBLK * 16)

// ---------------- device global scratch (static allocation only) ----------------
__device__ __align__(16) float d_OUT[SEQ * DECIN];          // [emb | val | hx_pre]
__device__ __align__(16) float d_PQ[SEQ * QIN];
__device__ __align__(16) float d_PI[SEQ * GATES];
__device__ __align__(16) float d_Wq1T[QIN * QIN];
__device__ __align__(16) float d_Wq2T[QUERY * QIN];
__device__ __align__(16) float d_kbvT[(VALUE + 1) * NKBP];  // row 512 = ones
__device__ __align__(16) float d_bihh[GATES];
__device__ __align__(16) float d_hx[2][STATE];
__device__ __align__(16) float d_cx[STATE];
__device__ __align__(16) float d_qh[QIN];
__device__ __align__(16) float d_qv[QUERY];
__device__ __align__(16) float d_w[NKBP];
__device__ __align__(16) float d_valU[VALUE + 4];
__device__ __align__(16) float d_ghx[GATES];
__device__ __align__(16) __nv_bfloat16 d_Abf[SEQ * DECIN];    // OUT in bf16
__device__ __align__(16) __nv_bfloat16 d_Wdbf[NTOK * DECIN];  // W_dec in bf16

__device__ unsigned d_flags[NBLK];
__device__ unsigned d_gen;

// ---------------- helpers ----------------
__device__ __forceinline__ float wred(float v) {
#pragma unroll
    for (int o = 16; o; o >>= 1) v += __shfl_xor_sync(0xffffffffu, v, o);
    return v;
}

// Flag-array grid barrier: each block release-stores its own flag (parallel,
// distinct addresses); block 0's warp 0 polls all flags in ~1 L2 round trip,
// then release-stores the generation. Acq/rel chain gives transitive
// visibility of all __stcg writes. No single-address atomic serialization.
__device__ __forceinline__ void gridbar(unsigned &mygen) {
    ++mygen;
    __syncthreads();
    if (blockIdx.x == 0) {
        if (threadIdx.x < 32) {
            bool done = false;
            while (!done) {
                unsigned mn = 0xffffffffu;
#pragma unroll
                for (int i = 0; i < 5; ++i) {
                    int b = 1 + (int)threadIdx.x + i * 32;
                    if (b < NBLK) {
                        unsigned f;
                        asm volatile("ld.acquire.gpu.global.u32 %0, [%1];"
                                     : "=r"(f) : "l"(&d_flags[b]) : "memory");
                        mn = min(mn, f);
                    }
                }
                done = __all_sync(0xffffffffu, (int)(mn >= mygen));
            }
            if (threadIdx.x == 0)
                asm volatile("st.release.gpu.global.u32 [%0], %1;"
                             :: "l"(&d_gen), "r"(mygen) : "memory");
        }
    } else {
        if (threadIdx.x == 0) {
            asm volatile("st.release.gpu.global.u32 [%0], %1;"
                         :: "l"(&d_flags[blockIdx.x]), "r"(mygen) : "memory");
            unsigned g;
            do {
                asm volatile("ld.acquire.gpu.global.u32 %0, [%1];"
                             : "=r"(g) : "l"(&d_gen) : "memory");
            } while (g < mygen);
        }
    }
    __syncthreads();
}

// ---------------- init: state, pads, fused bias, barrier reset ----------------
__global__ void init_k(const float* __restrict__ b_ih, const float* __restrict__ b_hh) {
    int i = blockIdx.x * blockDim.x + threadIdx.x;
    if (i == 0) d_gen = 0u;
    if (i < NBLK) d_flags[i] = 0u;
    if (i < STATE) { d_hx[0][i] = 0.f; d_hx[1][i] = 0.f; d_cx[i] = 0.f; }
    if (i < GATES) d_bihh[i] = b_ih[i] + b_hh[i];
    if (i < (NKBP - NKB)) d_w[NKB + i] = 0.f;
    if (i < (VALUE + 1) * (NKBP - NKB)) {
        int v = i / (NKBP - NKB);
        int n = NKB + i % (NKBP - NKB);
        d_kbvT[(size_t)v * NKBP + n] = 0.f;
    }
    if (i < NKB) d_kbvT[(size_t)VALUE * NKBP + i] = 1.f;
}

// ---------------- embedding gather ----------------
__global__ void embed_k(const int* __restrict__ ids, const float* __restrict__ encW) {
    int i = blockIdx.x * blockDim.x + threadIdx.x;
    if (i < SEQ * EMB) {
        int s = i >> 10, e = i & 1023;
        d_OUT[(size_t)s * DECIN + e] = encW[(size_t)ids[s] * EMB + e];
    }
}

// ---------------- transpose ----------------
__global__ void transpose_k(const float* __restrict__ S, float* __restrict__ D,
                            int R, int C, int dst) {
    long total = (long)R * C;
    for (long i = (long)blockIdx.x * blockDim.x + threadIdx.x; i < total;
         i += (long)gridDim.x * blockDim.x) {
        int r = (int)(i / C), c = (int)(i % C);
        D[(size_t)c * dst + r] = S[(size_t)r * C + c];
    }
}

// ---------------- fp32 -> bf16 conversion (n even) ----------------
__global__ void tobf16_k(const float* __restrict__ S, __nv_bfloat16* __restrict__ D, long n) {
    const float2* s2 = (const float2*)S;
    __nv_bfloat162* d2 = (__nv_bfloat162*)D;
    long half = n >> 1;
    for (long j = (long)blockIdx.x * blockDim.x + threadIdx.x; j < half;
         j += (long)gridDim.x * blockDim.x)
        d2[j] = __float22bfloat162_rn(s2[j]);
}

// ---------------- fp32 SIMT SGEMM (phase-A only): C = bias + A @ B^T ----------------
__global__ void __launch_bounds__(256) gemm_abt(
    const float* __restrict__ A, int lda,
    const float* __restrict__ B, int ldb,
    const float* __restrict__ bias,
    float* __restrict__ C, int ldc, int K)
{
    __shared__ float As[16][132];
    __shared__ float Bs[16][132];
    const int tid = threadIdx.x;
    const int m0 = blockIdx.x * 128, n0 = blockIdx.y * 128;
    const int lr = tid >> 2;
    const int lk = (tid & 3) * 4;
    const int tx = tid & 15, ty = tid >> 4;

    float acc[8][8];
#pragma unroll
    for (int i = 0; i < 8; ++i)
#pragma unroll
        for (int j = 0; j < 8; ++j) acc[i][j] = 0.f;

    for (int k0 = 0; k0 < K; k0 += 16) {
#pragma unroll
        for (int h = 0; h < 2; ++h) {
            int r = lr + h * 64;
            float4 a = *(const float4*)&A[(size_t)(m0 + r) * lda + k0 + lk];
            As[lk + 0][r] = a.x; As[lk + 1][r] = a.y;
            As[lk + 2][r] = a.z; As[lk + 3][r] = a.w;
            float4 b = *(const float4*)&B[(size_t)(n0 + r) * ldb + k0 + lk];
            Bs[lk + 0][r] = b.x; Bs[lk + 1][r] = b.y;
            Bs[lk + 2][r] = b.z; Bs[lk + 3][r] = b.w;
        }
        __syncthreads();
#pragma unroll
        for (int kk = 0; kk < 16; ++kk) {
            float av[8], bv[8];
            const float4* a4 = (const float4*)&As[kk][ty * 8];
            const float4* b4 = (const float4*)&Bs[kk][tx * 8];
            float4 a0 = a4[0], a1 = a4[1];
            float4 b0 = b4[0], b1 = b4[1];
            av[0] = a0.x; av[1] = a0.y; av[2] = a0.z; av[3] = a0.w;
            av[4] = a1.x; av[5] = a1.y; av[6] = a1.z; av[7] = a1.w;
            bv[0] = b0.x; bv[1] = b0.y; bv[2] = b0.z; bv[3] = b0.w;
            bv[4] = b1.x; bv[5] = b1.y; bv[6] = b1.z; bv[7] = b1.w;
#pragma unroll
            for (int i = 0; i < 8; ++i)
#pragma unroll
                for (int j = 0; j < 8; ++j) acc[i][j] += av[i] * bv[j];
        }
        __syncthreads();
    }
#pragma unroll
    for (int i = 0; i < 8; ++i) {
        int row = m0 + ty * 8 + i;
#pragma unroll
        for (int j = 0; j < 8; ++j) {
            int col = n0 + tx * 8 + j;
            C[(size_t)row * ldc + col] = acc[i][j] + __ldg(&bias[col]);
        }
    }
}

// ---------------- bf16 tensor-core GEMM: C[m][n] = bias[n] + A[m] . B[n] ----------------
// A [M][lda] bf16 row-major, B [N][ldb] bf16 row-major (B^T applied).
// Tile 128x128, KC=32, 8 warps (4 m x 2 n), warp tile 32x64, mma m16n8k16.
__global__ void __launch_bounds__(256) gemm_bf16_mma(
    const __nv_bfloat16* __restrict__ A, int lda,
    const __nv_bfloat16* __restrict__ B, int ldb,
    const float* __restrict__ bias,
    float* __restrict__ C, int ldc, int K)
{
    __shared__ unsigned As[128][17];   // 16 used cols (32 bf16), pad 17
    __shared__ unsigned Bs[128][17];
    const int tid = threadIdx.x;
    const int wid = tid >> 5, lane = tid & 31;
    const int wm = wid & 3, wn = wid >> 2;
    const int m0 = blockIdx.x * 128, n0 = blockIdx.y * 128;
    const int r = lane >> 2, kp = lane & 3;

    float acc[2][8][4];
#pragma unroll
    for (int mt = 0; mt < 2; ++mt)
#pragma unroll
        for (int nt = 0; nt < 8; ++nt)
#pragma unroll
            for (int c = 0; c < 4; ++c) acc[mt][nt][c] = 0.f;

    for (int k0 = 0; k0 < K; k0 += 32) {
        // load A,B tiles: 128 rows x 32 bf16 each = 2048 uints; 8 uints/thread via 2 uint4
#pragma unroll
        for (int i = 0; i < 2; ++i) {
            int idx = tid + i * 256;           // 0..511
            int row = idx >> 2, q = idx & 3;   // 4 uint4 per row
            uint4 va = *(const uint4*)&A[(size_t)(m0 + row) * lda + k0 + q * 8];
            As[row][q * 4 + 0] = va.x; As[row][q * 4 + 1] = va.y;
            As[row][q * 4 + 2] = va.z; As[row][q * 4 + 3] = va.w;
            uint4 vb = *(const uint4*)&B[(size_t)(n0 + row) * ldb + k0 + q * 8];
            Bs[row][q * 4 + 0] = vb.x; Bs[row][q * 4 + 1] = vb.y;
            Bs[row][q * 4 + 2] = vb.z; Bs[row][q * 4 + 3] = vb.w;
        }
        __syncthreads();
#pragma unroll
        for (int kk = 0; kk < 2; ++kk) {
            const int kb = kk * 8;
            unsigned afr[2][4];
#pragma unroll
            for (int mt = 0; mt < 2; ++mt) {
                int row = wm * 32 + mt * 16 + r;
                afr[mt][0] = As[row][kb + kp];
                afr[mt][1] = As[row + 8][kb + kp];
                afr[mt][2] = As[row][kb + kp + 4];
                afr[mt][3] = As[row + 8][kb + kp + 4];
            }
#pragma unroll
            for (int nt = 0; nt < 8; ++nt) {
                int brow = wn * 64 + nt * 8 + r;
                unsigned b0 = Bs[brow][kb + kp];
                unsigned b1 = Bs[brow][kb + kp + 4];
#pragma unroll
                for (int mt = 0; mt < 2; ++mt) {
                    asm volatile(
                        "mma.sync.aligned.m16n8k16.row.col.f32.bf16.bf16.f32 "
                        "{%0,%1,%2,%3}, {%4,%5,%6,%7}, {%8,%9}, {%0,%1,%2,%3};"
                        : "+f"(acc[mt][nt][0]), "+f"(acc[mt][nt][1]),
                          "+f"(acc[mt][nt][2]), "+f"(acc[mt][nt][3])
                        : "r"(afr[mt][0]), "r"(afr[mt][1]),
                          "r"(afr[mt][2]), "r"(afr[mt][3]),
                          "r"(b0), "r"(b1));
                }
            }
        }
        __syncthreads();
    }
#pragma unroll
    for (int mt = 0; mt < 2; ++mt) {
#pragma unroll
        for (int nt = 0; nt < 8; ++nt) {
            int row = m0 + wm * 32 + mt * 16 + r;
            int col = n0 + wn * 64 + nt * 8 + 2 * kp;
            float b0 = __ldg(&bias[col]), b1 = __ldg(&bias[col + 1]);
            *(float2*)&C[(size_t)row * ldc + col] =
                make_float2(acc[mt][nt][0] + b0, acc[mt][nt][1] + b1);
            *(float2*)&C[(size_t)(row + 8) * ldc + col] =
                make_float2(acc[mt][nt][2] + b0, acc[mt][nt][3] + b1);
        }
    }
}

// ---------------- persistent recurrence kernel ----------------
__global__ void __launch_bounds__(NTHR, 1) recur_k(
    const float* __restrict__ kb_keys,
    const float* __restrict__ W_ih,
    const float* __restrict__ W_hh,
    const float* __restrict__ bq2)
{
    __shared__ __align__(16) float sb[NKBP];   // 40 KB staging buffer
    float4* sb4 = (float4*)sb;
    const int tid  = threadIdx.x;
    const int lane = tid & 31;
    const int wrp  = tid >> 5;
    const int W    = blockIdx.x * 16 + wrp;
    const int gid  = blockIdx.x * NTHR + tid;
    unsigned mygen = 0;

    for (int t = 0; t < SEQ; ++t) {
        const int p = t & 1;

        // ======== stage A: qh = tanh(PQ + hx@Wq1_hx); ghx = hx@W_hh.T ========
        if (tid < STATE / 4) sb4[tid] = __ldcg((const float4*)&d_hx[p][0] + tid);
        if (gid < QUERY)     d_qv[gid]   = 0.f;
        if (gid < VALUE + 1) d_valU[gid] = 0.f;
        __syncthreads();
        {
            const float* pq = d_PQ + (size_t)t * QIN;
            for (int r = W; r < QIN + GATES; r += NWTOT) {
                const float4* wr4 = (r < QIN)
                    ? (const float4*)(d_Wq1T + (size_t)r * QIN)
                    : (const float4*)(W_hh + (size_t)(r - QIN) * STATE);
                float s = 0.f;
#pragma unroll
                for (int u = 0; u < 8; ++u) {
                    float4 w = __ldcg(&wr4[u * 32 + lane]);
                    float4 h = sb4[u * 32 + lane];
                    s += w.x * h.x + w.y * h.y + w.z * h.z + w.w * h.w;
                }
                s = wred(s);
                if (lane == 0) {
                    if (r < QIN) __stcg(&d_qh[r], tanhf(__ldcg(&pq[r]) + s));
                    else         __stcg(&d_ghx[r - QIN], s);
                }
            }
        }
        gridbar(mygen);

        // ======== stage B: q = qh @ Wq2 + bq2 (4 x 512 chunks) ========
        for (int i = tid; i < QIN / 4; i += NTHR) sb4[i] = __ldcg((const float4*)d_qh + i);
        __syncthreads();
        for (int task = W; task < QUERY * 4; task += NWTOT) {
            int k = task >> 2, c = task & 3;
            const float4* wr4 = (const float4*)(d_Wq2T + (size_t)k * QIN + c * 512);
            float s = 0.f;
#pragma unroll
            for (int u = 0; u < 4; ++u) {
                float4 w = __ldcg(&wr4[u * 32 + lane]);
                float4 q = sb4[c * 128 + u * 32 + lane];
                s += w.x * q.x + w.y * q.y + w.z * q.z + w.w * q.w;
            }
            s = wred(s);
            if (lane == 0) {
                if (c == 0) s += __ldg(&bq2[k]);
                atomicAdd(&d_qv[k], s);
            }
        }
        gridbar(mygen);

        // ======== stage C: w[n] = exp(kb_keys[n] . q) (logits O(10), no max shift) ========
        if (tid < QUERY / 4) sb4[tid] = __ldcg((const float4*)d_qv + tid);
        __syncthreads();
        for (int n = W; n < NKB; n += NWTOT) {
            const float4* kr4 = (const float4*)(kb_keys + (size_t)n * QUERY);
            float s = 0.f;
#pragma unroll
            for (int u = 0; u < 2; ++u) {
                float4 w = __ldcg(&kr4[u * 32 + lane]);
                float4 q = sb4[u * 32 + lane];
                s += w.x * q.x + w.y * q.y + w.z * q.z + w.w * q.w;
            }
            s = wred(s);
            if (lane == 0) __stcg(&d_w[n], expf(s));
        }
        gridbar(mygen);

        // ======== stage D: valU[v] = w . kbvT[v]; valU[512] = sum w ========
        for (int i = tid; i < NKBP / 4; i += NTHR) sb4[i] = __ldcg((const float4*)d_w + i);
        __syncthreads();
        for (int task = W; task < (VALUE + 1) * 8; task += NWTOT) {
            int v = task >> 3, c = task & 7;
            const float4* kr4 = (const float4*)(d_kbvT + (size_t)v * NKBP + c * 1280);
            const float4* ws4 = sb4 + c * 320;
            float s = 0.f;
#pragma unroll
            for (int u = 0; u < 10; ++u) {
                float4 w = __ldcg(&kr4[u * 32 + lane]);
                float4 x = ws4[u * 32 + lane];
                s += w.x * x.x + w.y * x.y + w.z * x.z + w.w * x.w;
            }
            s = wred(s);
            if (lane == 0) atomicAdd(&d_valU[v], s);
        }
        gridbar(mygen);

        // ======== stage E: gates + LSTM pointwise + write OUT row ========
        if (tid < VALUE / 4) sb4[tid] = __ldcg((const float4*)d_valU + tid);
        if (tid == NTHR - 1) sb[VALUE] = __ldcg(&d_valU[VALUE]);
        __syncthreads();
        {
            const float inv = 1.f / sb[VALUE];
            float* outrow = d_OUT + (size_t)t * DECIN;
            const float* pi = d_PI + (size_t)t * GATES;
            for (int task = W; task < STATE + 16; task += NWTOT) {
                if (task < STATE) {
                    const int i = task;
                    const float4* w0 = (const float4*)(W_ih + (size_t)(i            ) * LIN + EMB);
                    const float4* w1 = (const float4*)(W_ih + (size_t)(i +     STATE) * LIN + EMB);
                    const float4* w2 = (const float4*)(W_ih + (size_t)(i + 2 * STATE) * LIN + EMB);
                    const float4* w3 = (const float4*)(W_ih + (size_t)(i + 3 * STATE) * LIN + EMB);
                    float s0 = 0.f, s1 = 0.f, s2 = 0.f, s3 = 0.f;
#pragma unroll
                    for (int u = 0; u < 4; ++u) {
                        float4 v4 = sb4[u * 32 + lane];
                        float4 a = __ldcg(&w0[u * 32 + lane]);
                        float4 b = __ldcg(&w1[u * 32 + lane]);
                        float4 c = __ldcg(&w2[u * 32 + lane]);
                        float4 d = __ldcg(&w3[u * 32 + lane]);
                        s0 += a.x * v4.x + a.y * v4.y + a.z * v4.z + a.w * v4.w;
                        s1 += b.x * v4.x + b.y * v4.y + b.z * v4.z + b.w * v4.w;
                        s2 += c.x * v4.x + c.y * v4.y + c.z * v4.z + c.w * v4.w;
                        s3 += d.x * v4.x + d.y * v4.y + d.z * v4.z + d.w * v4.w;
                    }
                    s0 = wred(s0); s1 = wred(s1); s2 = wred(s2); s3 = wred(s3);
                    if (lane == 0) {
                        float gi = __ldcg(&pi[i])             + __ldcg(&d_ghx[i])             + s0 * inv;
                        float gf = __ldcg(&pi[i + STATE])     + __ldcg(&d_ghx[i + STATE])     + s1 * inv;
                        float gG = __ldcg(&pi[i + 2 * STATE]) + __ldcg(&d_ghx[i + 2 * STATE]) + s2 * inv;
                        float go = __ldcg(&pi[i + 3 * STATE]) + __ldcg(&d_ghx[i + 3 * STATE]) + s3 * inv;
                        float hpre = __ldcg(&d_hx[p][i]);
                        float ii = 1.f / (1.f + expf(-gi));
                        float ff = 1.f / (1.f + expf(-gf));
                        float g2 = tanhf(gG);
                        float oo = 1.f / (1.f + expf(-go));
                        float cn = ff * __ldcg(&d_cx[i]) + ii * g2;
                        float hn = oo * tanhf(cn);
                        __stcg(&d_cx[i], cn);
                        __stcg(&d_hx[1 - p][i], hn);
                        outrow[EMB + VALUE + i] = hpre;
                    }
                } else {
                    int vb = (task - STATE) * 32 + lane;   // 16 warps x 32 = 512
                    outrow[EMB + vb] = sb[vb] * inv;
                }
            }
        }
        gridbar(mygen);
    }
}

// ---------------- row-wise log-softmax (in place) ----------------
__global__ void __launch_bounds__(256) logsoftmax_k(float* __restrict__ X) {
    const int row = blockIdx.x;
    float* x = X + (size_t)row * NTOK;
    __shared__ float sred[8];
    const int tid = threadIdx.x, lane = tid & 31, w = tid >> 5;

    float m = -1e30f;
    for (int i = tid; i < NTOK; i += 256) m = fmaxf(m, x[i]);
#pragma unroll
    for (int o = 16; o; o >>= 1) m = fmaxf(m, __shfl_xor_sync(0xffffffffu, m, o));
    if (lane == 0) sred[w] = m;
    __syncthreads();
    if (tid == 0) {
        float v = sred[0];
#pragma unroll
        for (int j = 1; j < 8; ++j) v = fmaxf(v, sred[j]);
        sred[0] = v;
    }
    __syncthreads();
    m = sred[0];
    __syncthreads();

    float s = 0.f;
    for (int i = tid; i < NTOK; i += 256) s += expf(x[i] - m);
    s = wred(s);
    if (lane == 0) sred[w] = s;
    __syncthreads();
    if (tid == 0) {
        float v = 0.f;
#pragma unroll
        for (int j = 0; j < 8; ++j) v += sred[j];
        sred[0] = v;
    }
    __syncthreads();
    const float lse = m + logf(sred[0]);

    for (int i = tid; i < NTOK; i += 256) x[i] = x[i] - lse;
}

// ---------------- launch ----------------
extern "C" void kernel_launch(void* const* d_in, const int* in_sizes, int n_in,
                              void* d_out, int out_size) {
    const int*   ids     = (const int*)  d_in[0];
    const float* enc_W   = (const float*)d_in[1];
    const float* Wq1     = (const float*)d_in[2];
    const float* bq1     = (const float*)d_in[3];
    const float* Wq2     = (const float*)d_in[4];
    const float* bq2     = (const float*)d_in[5];
    const float* kb_keys = (const float*)d_in[6];
    const float* kb_vals = (const float*)d_in[7];
    const float* W_ih    = (const float*)d_in[8];
    const float* b_ih    = (const float*)d_in[9];
    const float* W_hh    = (const float*)d_in[10];
    const float* b_hh    = (const float*)d_in[11];
    const float* W_dec   = (const float*)d_in[12];
    const float* b_dec   = (const float*)d_in[13];
    float* out = (float*)d_out;

    float* wq1t_dev = nullptr; cudaGetSymbolAddress((void**)&wq1t_dev, d_Wq1T);
    float* wq2t_dev = nullptr; cudaGetSymbolAddress((void**)&wq2t_dev, d_Wq2T);
    float* kbvt_dev = nullptr; cudaGetSymbolAddress((void**)&kbvt_dev, d_kbvT);
    float* out_dev  = nullptr; cudaGetSymbolAddress((void**)&out_dev,  d_OUT);
    float* pq_dev   = nullptr; cudaGetSymbolAddress((void**)&pq_dev,   d_PQ);
    float* pi_dev   = nullptr; cudaGetSymbolAddress((void**)&pi_dev,   d_PI);
    float* bihh_dev = nullptr; cudaGetSymbolAddress((void**)&bihh_dev, d_bihh);
    __nv_bfloat16* abf_dev = nullptr; cudaGetSymbolAddress((void**)&abf_dev, d_Abf);
    __nv_bfloat16* wdb_dev = nullptr; cudaGetSymbolAddress((void**)&wdb_dev, d_Wdbf);

    // 1) init (state zero, pads, ones row, fused bias, barrier reset)
    init_k<<<((VALUE + 1) * (NKBP - NKB) + 255) / 256, 256>>>(b_ih, b_hh);
    // 2) embedding gather
    embed_k<<<(SEQ * EMB + 255) / 256, 256>>>(ids, enc_W);
    // 3) transposes + W_dec -> bf16
    transpose_k<<<4096, 256>>>(Wq1,     wq1t_dev, QIN, QIN,   QIN);
    transpose_k<<<2048, 256>>>(Wq2,     wq2t_dev, QIN, QUERY, QIN);
    transpose_k<<<4096, 256>>>(kb_vals, kbvt_dev, NKB, VALUE, NKBP);
    tobf16_k<<<4096, 256>>>(W_dec, wdb_dev, (long)NTOK * DECIN);
    // 4) PQ = emb @ Wq1[x-part] + bq1
    gemm_abt<<<dim3(SEQ / 128, QIN / 128), 256>>>(
        out_dev, DECIN, wq1t_dev + EMB, QIN, bq1, pq_dev, QIN, EMB);
    // 5) PI = emb @ W_ih[:, :1024].T + (b_ih + b_hh)
    gemm_abt<<<dim3(SEQ / 128, GATES / 128), 256>>>(
        out_dev, DECIN, W_ih, LIN, bihh_dev, pi_dev, GATES, EMB);
    // 6) persistent recurrence
    recur_k<<<NBLK, NTHR>>>(kb_keys, W_ih, W_hh, bq2);
    // 7) OUT -> bf16, then tensor-core decoder GEMM
    tobf16_k<<<2048, 256>>>(out_dev, abf_dev, (long)SEQ * DECIN);
    gemm_bf16_mma<<<dim3(SEQ / 128, NTOK / 128), 256>>>(
        abf_dev, DECIN, wdb_dev, DECIN, b_dec, out, NTOK, DECIN);
    // 8) log-softmax in place
    logsoftmax_k<<<SEQ, 256>>>(out);
}

// round 12
// speedup vs baseline: 1.2616x; 1.2616x over previous
#include <cuda_runtime.h>
#include <cuda_bf16.h>
#include <math.h>

#define SEQ    2048
#define EMB    1024
#define STATE  1024
#define QIN    2048
#define QUERY  256
#define NKB    10000
#define NKBP   10240
#define VALUE  512
#define NTOK   32000
#define DECIN  2560
#define GATES  4096
#define LIN    1536

#define NBLK   148
#define NTHR   512
#define NWTOT  (NBLK * 16)

// ---------------- device global scratch (static allocation only) ----------------
__device__ __align__(16) float d_OUT[SEQ * DECIN];          // [emb | val | hx_pre]
__device__ __align__(16) float d_PQ[SEQ * QIN];
__device__ __align__(16) float d_PI[SEQ * GATES];
__device__ __align__(16) float d_Wq1T[QIN * QIN];
__device__ __align__(16) float d_Wq2T[QUERY * QIN];
__device__ __align__(16) __nv_bfloat16 d_kbvB[(VALUE + 1) * NKBP]; // bf16; row 512 = ones
__device__ __align__(16) float d_bihh[GATES];
__device__ __align__(16) float d_hx[2][STATE];
__device__ __align__(16) float d_cx[STATE];
__device__ __align__(16) float d_qh[QIN];
__device__ __align__(16) float d_qv[QUERY];
__device__ __align__(16) float d_w[NKBP];
__device__ __align__(16) float d_valU[VALUE + 4];
__device__ __align__(16) float d_ghx[GATES];
__device__ __align__(16) __nv_bfloat16 d_Abf[SEQ * DECIN];    // OUT in bf16
__device__ __align__(16) __nv_bfloat16 d_Wdbf[NTOK * DECIN];  // W_dec in bf16

__device__ unsigned d_cnt;
__device__ unsigned d_gen;

// ---------------- helpers ----------------
__device__ __forceinline__ float wred(float v) {
#pragma unroll
    for (int o = 16; o; o >>= 1) v += __shfl_xor_sync(0xffffffffu, v, o);
    return v;
}

// R9 grid barrier (measured-good): monotonic generation counter; release on
// arrive, acquire on spin. Last arriver releases d_gen directly — one hop.
// All cross-block traffic in recur_k uses __ldcg/__stcg (L2-coherent).
__device__ __forceinline__ void gridbar(unsigned &mygen) {
    __syncthreads();
    if (threadIdx.x == 0) {
        ++mygen;
        unsigned prev;
        asm volatile("atom.release.gpu.global.add.u32 %0, [%1], %2;"
                     : "=r"(prev) : "l"(&d_cnt), "r"(1u) : "memory");
        if (prev % NBLK == NBLK - 1) {
            asm volatile("st.release.gpu.global.u32 [%0], %1;"
                         :: "l"(&d_gen), "r"(mygen) : "memory");
        } else {
            unsigned g;
            do {
                asm volatile("ld.acquire.gpu.global.u32 %0, [%1];"
                             : "=r"(g) : "l"(&d_gen) : "memory");
            } while (g < mygen);
        }
    }
    __syncthreads();
}

// ---------------- init: state, pads, fused bias, barrier reset ----------------
__global__ void init_k(const float* __restrict__ b_ih, const float* __restrict__ b_hh) {
    int i = blockIdx.x * blockDim.x + threadIdx.x;
    if (i == 0) { d_cnt = 0u; d_gen = 0u; }
    if (i < STATE) { d_hx[0][i] = 0.f; d_hx[1][i] = 0.f; d_cx[i] = 0.f; }
    if (i < GATES) d_bihh[i] = b_ih[i] + b_hh[i];
    if (i < (NKBP - NKB)) d_w[NKB + i] = 0.f;
    if (i < (VALUE + 1) * (NKBP - NKB)) {
        int v = i / (NKBP - NKB);
        int n = NKB + i % (NKBP - NKB);
        d_kbvB[(size_t)v * NKBP + n] = __float2bfloat16(0.f);
    }
    if (i < NKB) d_kbvB[(size_t)VALUE * NKBP + i] = __float2bfloat16(1.f);
}

// ---------------- embedding gather ----------------
__global__ void embed_k(const int* __restrict__ ids, const float* __restrict__ encW) {
    int i = blockIdx.x * blockDim.x + threadIdx.x;
    if (i < SEQ * EMB) {
        int s = i >> 10, e = i & 1023;
        d_OUT[(size_t)s * DECIN + e] = encW[(size_t)ids[s] * EMB + e];
    }
}

// ---------------- fused one-time prep: transposes + bf16 conversions ----------------
// Output-major iteration (coalesced writes); scattered reads are absorbed by L2
// (each source fits in L2, lines reused across output passes).
__global__ void prep_k(const float* __restrict__ Wq1, const float* __restrict__ Wq2,
                       const float* __restrict__ kb_vals, const float* __restrict__ W_dec) {
    const long stride = (long)gridDim.x * blockDim.x;
    const long t0 = (long)blockIdx.x * blockDim.x + threadIdx.x;
    // 1) Wq1T[r][c] = Wq1[c][r]
    for (long j = t0; j < (long)QIN * QIN; j += stride) {
        int r = (int)(j >> 11), c = (int)(j & (QIN - 1));
        d_Wq1T[j] = Wq1[(size_t)c * QIN + r];
    }
    // 2) Wq2T[k][jj] = Wq2[jj][k]
    for (long j = t0; j < (long)QUERY * QIN; j += stride) {
        int k = (int)(j >> 11), jj = (int)(j & (QIN - 1));
        d_Wq2T[j] = Wq2[(size_t)jj * QUERY + k];
    }
    // 3) kbvB[v][n] = bf16(kb_vals[n][v])
    for (long j = t0; j < (long)VALUE * NKB; j += stride) {
        int v = (int)(j / NKB), n = (int)(j % NKB);
        d_kbvB[(size_t)v * NKBP + n] = __float2bfloat16(kb_vals[(size_t)n * VALUE + v]);
    }
    // 4) W_dec -> bf16
    const float2* s2 = (const float2*)W_dec;
    __nv_bfloat162* dd = (__nv_bfloat162*)d_Wdbf;
    for (long j = t0; j < (long)NTOK * DECIN / 2; j += stride)
        dd[j] = __float22bfloat162_rn(s2[j]);
}

// ---------------- fp32 -> bf16 conversion (n even) ----------------
__global__ void tobf16_k(const float* __restrict__ S, __nv_bfloat16* __restrict__ D, long n) {
    const float2* s2 = (const float2*)S;
    __nv_bfloat162* d2 = (__nv_bfloat162*)D;
    long half = n >> 1;
    for (long j = (long)blockIdx.x * blockDim.x + threadIdx.x; j < half;
         j += (long)gridDim.x * blockDim.x)
        d2[j] = __float22bfloat162_rn(s2[j]);
}

// ---------------- fp32 SIMT SGEMM (phase-A only): C = bias + A @ B^T ----------------
__global__ void __launch_bounds__(256) gemm_abt(
    const float* __restrict__ A, int lda,
    const float* __restrict__ B, int ldb,
    const float* __restrict__ bias,
    float* __restrict__ C, int ldc, int K)
{
    __shared__ float As[16][132];
    __shared__ float Bs[16][132];
    const int tid = threadIdx.x;
    const int m0 = blockIdx.x * 128, n0 = blockIdx.y * 128;
    const int lr = tid >> 2;
    const int lk = (tid & 3) * 4;
    const int tx = tid & 15, ty = tid >> 4;

    float acc[8][8];
#pragma unroll
    for (int i = 0; i < 8; ++i)
#pragma unroll
        for (int j = 0; j < 8; ++j) acc[i][j] = 0.f;

    for (int k0 = 0; k0 < K; k0 += 16) {
#pragma unroll
        for (int h = 0; h < 2; ++h) {
            int r = lr + h * 64;
            float4 a = *(const float4*)&A[(size_t)(m0 + r) * lda + k0 + lk];
            As[lk + 0][r] = a.x; As[lk + 1][r] = a.y;
            As[lk + 2][r] = a.z; As[lk + 3][r] = a.w;
            float4 b = *(const float4*)&B[(size_t)(n0 + r) * ldb + k0 + lk];
            Bs[lk + 0][r] = b.x; Bs[lk + 1][r] = b.y;
            Bs[lk + 2][r] = b.z; Bs[lk + 3][r] = b.w;
        }
        __syncthreads();
#pragma unroll
        for (int kk = 0; kk < 16; ++kk) {
            float av[8], bv[8];
            const float4* a4 = (const float4*)&As[kk][ty * 8];
            const float4* b4 = (const float4*)&Bs[kk][tx * 8];
            float4 a0 = a4[0], a1 = a4[1];
            float4 b0 = b4[0], b1 = b4[1];
            av[0] = a0.x; av[1] = a0.y; av[2] = a0.z; av[3] = a0.w;
            av[4] = a1.x; av[5] = a1.y; av[6] = a1.z; av[7] = a1.w;
            bv[0] = b0.x; bv[1] = b0.y; bv[2] = b0.z; bv[3] = b0.w;
            bv[4] = b1.x; bv[5] = b1.y; bv[6] = b1.z; bv[7] = b1.w;
#pragma unroll
            for (int i = 0; i < 8; ++i)
#pragma unroll
                for (int j = 0; j < 8; ++j) acc[i][j] += av[i] * bv[j];
        }
        __syncthreads();
    }
#pragma unroll
    for (int i = 0; i < 8; ++i) {
        int row = m0 + ty * 8 + i;
#pragma unroll
        for (int j = 0; j < 8; ++j) {
            int col = n0 + tx * 8 + j;
            C[(size_t)row * ldc + col] = acc[i][j] + __ldg(&bias[col]);
        }
    }
}

// ---------------- bf16 tensor-core GEMM: C[m][n] = bias[n] + A[m] . B[n] ----------------
__global__ void __launch_bounds__(256) gemm_bf16_mma(
    const __nv_bfloat16* __restrict__ A, int lda,
    const __nv_bfloat16* __restrict__ B, int ldb,
    const float* __restrict__ bias,
    float* __restrict__ C, int ldc, int K)
{
    __shared__ unsigned As[128][17];
    __shared__ unsigned Bs[128][17];
    const int tid = threadIdx.x;
    const int wid = tid >> 5, lane = tid & 31;
    const int wm = wid & 3, wn = wid >> 2;
    const int m0 = blockIdx.x * 128, n0 = blockIdx.y * 128;
    const int r = lane >> 2, kp = lane & 3;

    float acc[2][8][4];
#pragma unroll
    for (int mt = 0; mt < 2; ++mt)
#pragma unroll
        for (int nt = 0; nt < 8; ++nt)
#pragma unroll
            for (int c = 0; c < 4; ++c) acc[mt][nt][c] = 0.f;

    for (int k0 = 0; k0 < K; k0 += 32) {
#pragma unroll
        for (int i = 0; i < 2; ++i) {
            int idx = tid + i * 256;
            int row = idx >> 2, q = idx & 3;
            uint4 va = *(const uint4*)&A[(size_t)(m0 + row) * lda + k0 + q * 8];
            As[row][q * 4 + 0] = va.x; As[row][q * 4 + 1] = va.y;
            As[row][q * 4 + 2] = va.z; As[row][q * 4 + 3] = va.w;
            uint4 vb = *(const uint4*)&B[(size_t)(n0 + row) * ldb + k0 + q * 8];
            Bs[row][q * 4 + 0] = vb.x; Bs[row][q * 4 + 1] = vb.y;
            Bs[row][q * 4 + 2] = vb.z; Bs[row][q * 4 + 3] = vb.w;
        }
        __syncthreads();
#pragma unroll
        for (int kk = 0; kk < 2; ++kk) {
            const int kb = kk * 8;
            unsigned afr[2][4];
#pragma unroll
            for (int mt = 0; mt < 2; ++mt) {
                int row = wm * 32 + mt * 16 + r;
                afr[mt][0] = As[row][kb + kp];
                afr[mt][1] = As[row + 8][kb + kp];
                afr[mt][2] = As[row][kb + kp + 4];
                afr[mt][3] = As[row + 8][kb + kp + 4];
            }
#pragma unroll
            for (int nt = 0; nt < 8; ++nt) {
                int brow = wn * 64 + nt * 8 + r;
                unsigned b0 = Bs[brow][kb + kp];
                unsigned b1 = Bs[brow][kb + kp + 4];
#pragma unroll
                for (int mt = 0; mt < 2; ++mt) {
                    asm volatile(
                        "mma.sync.aligned.m16n8k16.row.col.f32.bf16.bf16.f32 "
                        "{%0,%1,%2,%3}, {%4,%5,%6,%7}, {%8,%9}, {%0,%1,%2,%3};"
                        : "+f"(acc[mt][nt][0]), "+f"(acc[mt][nt][1]),
                          "+f"(acc[mt][nt][2]), "+f"(acc[mt][nt][3])
                        : "r"(afr[mt][0]), "r"(afr[mt][1]),
                          "r"(afr[mt][2]), "r"(afr[mt][3]),
                          "r"(b0), "r"(b1));
                }
            }
        }
        __syncthreads();
    }
#pragma unroll
    for (int mt = 0; mt < 2; ++mt) {
#pragma unroll
        for (int nt = 0; nt < 8; ++nt) {
            int row = m0 + wm * 32 + mt * 16 + r;
            int col = n0 + wn * 64 + nt * 8 + 2 * kp;
            float b0 = __ldg(&bias[col]), b1 = __ldg(&bias[col + 1]);
            *(float2*)&C[(size_t)row * ldc + col] =
                make_float2(acc[mt][nt][0] + b0, acc[mt][nt][1] + b1);
            *(float2*)&C[(size_t)(row + 8) * ldc + col] =
                make_float2(acc[mt][nt][2] + b0, acc[mt][nt][3] + b1);
        }
    }
}

// ---------------- persistent recurrence kernel ----------------
__global__ void __launch_bounds__(NTHR, 1) recur_k(
    const float* __restrict__ kb_keys,
    const float* __restrict__ W_ih,
    const float* __restrict__ W_hh,
    const float* __restrict__ bq2)
{
    __shared__ __align__(16) float sb[NKBP];   // 40 KB staging buffer
    float4* sb4 = (float4*)sb;
    const int tid  = threadIdx.x;
    const int lane = tid & 31;
    const int wrp  = tid >> 5;
    const int W    = blockIdx.x * 16 + wrp;
    const int gid  = blockIdx.x * NTHR + tid;
    unsigned mygen = 0;

    for (int t = 0; t < SEQ; ++t) {
        const int p = t & 1;

        // ======== stage A: qh = tanh(PQ + hx@Wq1_hx); ghx = hx@W_hh.T ========
        if (tid < STATE / 4) sb4[tid] = __ldcg((const float4*)&d_hx[p][0] + tid);
        if (gid < QUERY)     d_qv[gid]   = 0.f;
        if (gid < VALUE + 1) d_valU[gid] = 0.f;
        __syncthreads();
        {
            const float* pq = d_PQ + (size_t)t * QIN;
            for (int r = W; r < QIN + GATES; r += NWTOT) {
                const float4* wr4 = (r < QIN)
                    ? (const float4*)(d_Wq1T + (size_t)r * QIN)
                    : (const float4*)(W_hh + (size_t)(r - QIN) * STATE);
                float s = 0.f;
#pragma unroll
                for (int u = 0; u < 8; ++u) {
                    float4 w = __ldcg(&wr4[u * 32 + lane]);
                    float4 h = sb4[u * 32 + lane];
                    s += w.x * h.x + w.y * h.y + w.z * h.z + w.w * h.w;
                }
                s = wred(s);
                if (lane == 0) {
                    if (r < QIN) __stcg(&d_qh[r], tanhf(__ldcg(&pq[r]) + s));
                    else         __stcg(&d_ghx[r - QIN], s);
                }
            }
        }
        gridbar(mygen);

        // ======== stage B: q = qh @ Wq2 + bq2 (4 x 512 chunks) ========
        for (int i = tid; i < QIN / 4; i += NTHR) sb4[i] = __ldcg((const float4*)d_qh + i);
        __syncthreads();
        for (int task = W; task < QUERY * 4; task += NWTOT) {
            int k = task >> 2, c = task & 3;
            const float4* wr4 = (const float4*)(d_Wq2T + (size_t)k * QIN + c * 512);
            float s = 0.f;
#pragma unroll
            for (int u = 0; u < 4; ++u) {
                float4 w = __ldcg(&wr4[u * 32 + lane]);
                float4 q = sb4[c * 128 + u * 32 + lane];
                s += w.x * q.x + w.y * q.y + w.z * q.z + w.w * q.w;
            }
            s = wred(s);
            if (lane == 0) {
                if (c == 0) s += __ldg(&bq2[k]);
                atomicAdd(&d_qv[k], s);
            }
        }
        gridbar(mygen);

        // ======== stage C: w[n] = exp(kb_keys[n] . q) (logits O(10), no max shift) ========
        if (tid < QUERY / 4) sb4[tid] = __ldcg((const float4*)d_qv + tid);
        __syncthreads();
        for (int n = W; n < NKB; n += NWTOT) {
            const float4* kr4 = (const float4*)(kb_keys + (size_t)n * QUERY);
            float s = 0.f;
#pragma unroll
            for (int u = 0; u < 2; ++u) {
                float4 w = __ldcg(&kr4[u * 32 + lane]);
                float4 q = sb4[u * 32 + lane];
                s += w.x * q.x + w.y * q.y + w.z * q.z + w.w * q.w;
            }
            s = wred(s);
            if (lane == 0) __stcg(&d_w[n], expf(s));
        }
        gridbar(mygen);

        // ======== stage D: valU[v] = w . kbvB[v] (bf16); valU[512] = sum w ========
        for (int i = tid; i < NKBP / 4; i += NTHR) sb4[i] = __ldcg((const float4*)d_w + i);
        __syncthreads();
        for (int task = W; task < (VALUE + 1) * 8; task += NWTOT) {
            int v = task >> 3, c = task & 7;
            const uint4* kr4 = (const uint4*)(d_kbvB + (size_t)v * NKBP + c * 1280);
            float s = 0.f;
#pragma unroll
            for (int u = 0; u < 5; ++u) {
                uint4 wv = __ldcg(&kr4[u * 32 + lane]);
                int fi = (c * 320 + (u * 32 + lane) * 2);
                float4 x0 = sb4[fi], x1 = sb4[fi + 1];
                float2 f0 = __bfloat1622float2(*(__nv_bfloat162*)&wv.x);
                float2 f1 = __bfloat1622float2(*(__nv_bfloat162*)&wv.y);
                float2 f2 = __bfloat1622float2(*(__nv_bfloat162*)&wv.z);
                float2 f3 = __bfloat1622float2(*(__nv_bfloat162*)&wv.w);
                s += f0.x * x0.x + f0.y * x0.y + f1.x * x0.z + f1.y * x0.w;
                s += f2.x * x1.x + f2.y * x1.y + f3.x * x1.z + f3.y * x1.w;
            }
            s = wred(s);
            if (lane == 0) atomicAdd(&d_valU[v], s);
        }
        gridbar(mygen);

        // ======== stage E: gates + LSTM pointwise + write OUT row ========
        if (tid < VALUE / 4) sb4[tid] = __ldcg((const float4*)d_valU + tid);
        if (tid == NTHR - 1) sb[VALUE] = __ldcg(&d_valU[VALUE]);
        __syncthreads();
        {
            const float inv = 1.f / sb[VALUE];
            float* outrow = d_OUT + (size_t)t * DECIN;
            const float* pi = d_PI + (size_t)t * GATES;
            for (int task = W; task < STATE + 16; task += NWTOT) {
                if (task < STATE) {
                    const int i = task;
                    const float4* w0 = (const float4*)(W_ih + (size_t)(i            ) * LIN + EMB);
                    const float4* w1 = (const float4*)(W_ih + (size_t)(i +     STATE) * LIN + EMB);
                    const float4* w2 = (const float4*)(W_ih + (size_t)(i + 2 * STATE) * LIN + EMB);
                    const float4* w3 = (const float4*)(W_ih + (size_t)(i + 3 * STATE) * LIN + EMB);
                    float s0 = 0.f, s1 = 0.f, s2 = 0.f, s3 = 0.f;
#pragma unroll
                    for (int u = 0; u < 4; ++u) {
                        float4 v4 = sb4[u * 32 + lane];
                        float4 a = __ldcg(&w0[u * 32 + lane]);
                        float4 b = __ldcg(&w1[u * 32 + lane]);
                        float4 c = __ldcg(&w2[u * 32 + lane]);
                        float4 d = __ldcg(&w3[u * 32 + lane]);
                        s0 += a.x * v4.x + a.y * v4.y + a.z * v4.z + a.w * v4.w;
                        s1 += b.x * v4.x + b.y * v4.y + b.z * v4.z + b.w * v4.w;
                        s2 += c.x * v4.x + c.y * v4.y + c.z * v4.z + c.w * v4.w;
                        s3 += d.x * v4.x + d.y * v4.y + d.z * v4.z + d.w * v4.w;
                    }
                    s0 = wred(s0); s1 = wred(s1); s2 = wred(s2); s3 = wred(s3);
                    if (lane == 0) {
                        float gi = __ldcg(&pi[i])             + __ldcg(&d_ghx[i])             + s0 * inv;
                        float gf = __ldcg(&pi[i + STATE])     + __ldcg(&d_ghx[i + STATE])     + s1 * inv;
                        float gG = __ldcg(&pi[i + 2 * STATE]) + __ldcg(&d_ghx[i + 2 * STATE]) + s2 * inv;
                        float go = __ldcg(&pi[i + 3 * STATE]) + __ldcg(&d_ghx[i + 3 * STATE]) + s3 * inv;
                        float hpre = __ldcg(&d_hx[p][i]);
                        float ii = 1.f / (1.f + expf(-gi));
                        float ff = 1.f / (1.f + expf(-gf));
                        float g2 = tanhf(gG);
                        float oo = 1.f / (1.f + expf(-go));
                        float cn = ff * __ldcg(&d_cx[i]) + ii * g2;
                        float hn = oo * tanhf(cn);
                        __stcg(&d_cx[i], cn);
                        __stcg(&d_hx[1 - p][i], hn);
                        outrow[EMB + VALUE + i] = hpre;
                    }
                } else {
                    int vb = (task - STATE) * 32 + lane;   // 16 warps x 32 = 512
                    outrow[EMB + vb] = sb[vb] * inv;
                }
            }
        }
        gridbar(mygen);
    }
}

// ---------------- row-wise log-softmax (in place) ----------------
__global__ void __launch_bounds__(256) logsoftmax_k(float* __restrict__ X) {
    const int row = blockIdx.x;
    float* x = X + (size_t)row * NTOK;
    __shared__ float sred[8];
    const int tid = threadIdx.x, lane = tid & 31, w = tid >> 5;

    float m = -1e30f;
    for (int i = tid; i < NTOK; i += 256) m = fmaxf(m, x[i]);
#pragma unroll
    for (int o = 16; o; o >>= 1) m = fmaxf(m, __shfl_xor_sync(0xffffffffu, m, o));
    if (lane == 0) sred[w] = m;
    __syncthreads();
    if (tid == 0) {
        float v = sred[0];
#pragma unroll
        for (int j = 1; j < 8; ++j) v = fmaxf(v, sred[j]);
        sred[0] = v;
    }
    __syncthreads();
    m = sred[0];
    __syncthreads();

    float s = 0.f;
    for (int i = tid; i < NTOK; i += 256) s += expf(x[i] - m);
    s = wred(s);
    if (lane == 0) sred[w] = s;
    __syncthreads();
    if (tid == 0) {
        float v = 0.f;
#pragma unroll
        for (int j = 0; j < 8; ++j) v += sred[j];
        sred[0] = v;
    }
    __syncthreads();
    const float lse = m + logf(sred[0]);

    for (int i = tid; i < NTOK; i += 256) x[i] = x[i] - lse;
}

// ---------------- launch ----------------
extern "C" void kernel_launch(void* const* d_in, const int* in_sizes, int n_in,
                              void* d_out, int out_size) {
    const int*   ids     = (const int*)  d_in[0];
    const float* enc_W   = (const float*)d_in[1];
    const float* Wq1     = (const float*)d_in[2];
    const float* bq1     = (const float*)d_in[3];
    const float* Wq2     = (const float*)d_in[4];
    const float* bq2     = (const float*)d_in[5];
    const float* kb_keys = (const float*)d_in[6];
    // kb_vals = d_in[7] consumed by prep_k
    const float* kb_vals = (const float*)d_in[7];
    const float* W_ih    = (const float*)d_in[8];
    const float* b_ih    = (const float*)d_in[9];
    const float* W_hh    = (const float*)d_in[10];
    const float* b_hh    = (const float*)d_in[11];
    const float* W_dec   = (const float*)d_in[12];
    const float* b_dec   = (const float*)d_in[13];
    float* out = (float*)d_out;

    float* wq1t_dev = nullptr; cudaGetSymbolAddress((void**)&wq1t_dev, d_Wq1T);
    float* out_dev  = nullptr; cudaGetSymbolAddress((void**)&out_dev,  d_OUT);
    float* pq_dev   = nullptr; cudaGetSymbolAddress((void**)&pq_dev,   d_PQ);
    float* pi_dev   = nullptr; cudaGetSymbolAddress((void**)&pi_dev,   d_PI);
    float* bihh_dev = nullptr; cudaGetSymbolAddress((void**)&bihh_dev, d_bihh);
    __nv_bfloat16* abf_dev = nullptr; cudaGetSymbolAddress((void**)&abf_dev, d_Abf);
    __nv_bfloat16* wdb_dev = nullptr; cudaGetSymbolAddress((void**)&wdb_dev, d_Wdbf);

    // Launch order keeps recur_k as the 6th launch (ncu -s 5 -c 1 captures it).
    // 1) init (state zero, pads, ones row, fused bias, barrier reset)
    init_k<<<((VALUE + 1) * (NKBP - NKB) + 255) / 256, 256>>>(b_ih, b_hh);
    // 2) embedding gather
    embed_k<<<(SEQ * EMB + 255) / 256, 256>>>(ids, enc_W);
    // 3) fused prep: transposes + kbv->bf16 + W_dec->bf16
    prep_k<<<2048, 256>>>(Wq1, Wq2, kb_vals, W_dec);
    // 4) PQ = emb @ Wq1[x-part] + bq1
    gemm_abt<<<dim3(SEQ / 128, QIN / 128), 256>>>(
        out_dev, DECIN, wq1t_dev + EMB, QIN, bq1, pq_dev, QIN, EMB);
    // 5) PI = emb @ W_ih[:, :1024].T + (b_ih + b_hh)
    gemm_abt<<<dim3(SEQ / 128, GATES / 128), 256>>>(
        out_dev, DECIN, W_ih, LIN, bihh_dev, pi_dev, GATES, EMB);
    // 6) persistent recurrence  <-- profiled launch
    recur_k<<<NBLK, NTHR>>>(kb_keys, W_ih, W_hh, bq2);
    // 7) OUT -> bf16, then tensor-core decoder GEMM
    tobf16_k<<<2048, 256>>>(out_dev, abf_dev, (long)SEQ * DECIN);
    gemm_bf16_mma<<<dim3(SEQ / 128, NTOK / 128), 256>>>(
        abf_dev, DECIN, wdb_dev, DECIN, b_dec, out, NTOK, DECIN);
    // 8) log-softmax in place
    logsoftmax_k<<<SEQ, 256>>>(out);
}